// round 8
// baseline (speedup 1.0000x reference)
#include <cuda_runtime.h>
#include <math.h>
#include <float.h>

#define BB 2
#define NN 8192
#define KK 16
#define CC 64
#define BN (BB*NN)

typedef unsigned long long ull;

__device__ __forceinline__ ull pk(float a, float b) {
    ull d; asm("mov.b64 %0,{%1,%2};" : "=l"(d) : "f"(a), "f"(b)); return d;
}
__device__ __forceinline__ void upk(ull s, float& a, float& b) {
    asm("mov.b64 {%0,%1},%2;" : "=f"(a), "=f"(b) : "l"(s));
}
__device__ __forceinline__ ull f2fma(ull a, ull b, ull c) {
    ull d; asm("fma.rn.f32x2 %0,%1,%2,%3;" : "=l"(d) : "l"(a), "l"(b), "l"(c)); return d;
}
__device__ __forceinline__ ull f2add(ull a, ull b) {
    ull d; asm("add.rn.f32x2 %0,%1,%2;" : "=l"(d) : "l"(a), "l"(b)); return d;
}

// scratch (device globals — no runtime allocation)
__device__ ull    g_q2[BN*32];     // (q[row][l], q[row][l+32])
__device__ ull    g_k2[BN*32];
__device__ ull    g_v2[BN*32];
__device__ int    g_idx[BN*KK];
__device__ float4 g_pos4[BN];      // (x, y, z, ||p||^2)
__device__ ulonglong2 g_wpe2[1024];  // packed weight pairs for attn (via L1)
__device__ ulonglong2 g_wat1[1024];
__device__ ulonglong2 g_wat2[1024];

// ---------------------------------------------------------------------------
// Kernel 0a: precompute pos4 with the exact fmaf chain used everywhere.
// ---------------------------------------------------------------------------
__global__ void prep_kernel(const float* __restrict__ pos) {
    int i = blockIdx.x * 256 + threadIdx.x;
    float x = pos[3 * i], y = pos[3 * i + 1], z = pos[3 * i + 2];
    g_pos4[i] = make_float4(x, y, z, fmaf(z, z, fmaf(y, y, x * x)));
}

// Kernel 0b: pack attn weights into (w[j][l], w[j][l+32]) pair-of-pairs.
__global__ void pack_kernel(const float* __restrict__ pe_w2,
                            const float* __restrict__ at_w1,
                            const float* __restrict__ at_w2) {
    int e = blockIdx.x * 256 + threadIdx.x;   // 0..1023
    int jp = e >> 5, l2 = e & 31;
    int j0 = 2 * jp, j1 = 2 * jp + 1;
    g_wpe2[e] = make_ulonglong2(pk(pe_w2[j0 * 64 + l2], pe_w2[j0 * 64 + l2 + 32]),
                                pk(pe_w2[j1 * 64 + l2], pe_w2[j1 * 64 + l2 + 32]));
    g_wat1[e] = make_ulonglong2(pk(at_w1[j0 * 64 + l2], at_w1[j0 * 64 + l2 + 32]),
                                pk(at_w1[j1 * 64 + l2], at_w1[j1 * 64 + l2 + 32]));
    g_wat2[e] = make_ulonglong2(pk(at_w2[j0 * 64 + l2], at_w2[j0 * 64 + l2 + 32]),
                                pk(at_w2[j1 * 64 + l2], at_w2[j1 * 64 + l2 + 32]));
}

// ---------------------------------------------------------------------------
// Kernel 1: x = feat@emb_w + emb_b ; q/k/v = x@wq/wk/wv.  (unchanged)
// ---------------------------------------------------------------------------
#define PW 4
__global__ void __launch_bounds__(128) proj_kernel(
        const float* __restrict__ feat,
        const float* __restrict__ emb_w, const float* __restrict__ emb_b,
        const float* __restrict__ wq, const float* __restrict__ wk,
        const float* __restrict__ wv) {
    extern __shared__ ull pu[];
    ull* we2 = pu;              // 2048
    ull* wq2 = pu + 2048;
    ull* wk2 = pu + 4096;
    ull* wv2 = pu + 6144;
    ull* Sbase = pu + 8192;     // PW * 576
    ull* ebp = Sbase + PW * 576; // 32

    int tid = threadIdx.x, lane = tid & 31, w = tid >> 5;
    for (int e = tid; e < 2048; e += 128) {
        int j = e >> 5, l2 = e & 31;
        we2[e] = pk(emb_w[j * 64 + l2], emb_w[j * 64 + l2 + 32]);
        wq2[e] = pk(wq[j * 64 + l2],   wq[j * 64 + l2 + 32]);
        wk2[e] = pk(wk[j * 64 + l2],   wk[j * 64 + l2 + 32]);
        wv2[e] = pk(wv[j * 64 + l2],   wv[j * 64 + l2 + 32]);
    }
    if (tid < 32) ebp[tid] = pk(emb_b[tid], emb_b[tid + 32]);

    int rows = (blockIdx.x * PW + w) * 16;
    ull* S = Sbase + w * 576;

#pragma unroll
    for (int rp = 0; rp < 8; rp++) {
        const float* f0 = feat + (size_t)(rows + 2 * rp) * 64;
        const float* f1 = f0 + 64;
        S[lane * 9 + rp]        = pk(f0[lane],      f1[lane]);
        S[(lane + 32) * 9 + rp] = pk(f0[lane + 32], f1[lane + 32]);
    }
    __syncthreads();

    ull xL[8], xH[8];
    {
        float bl, bh;
        upk(ebp[lane], bl, bh);
        ull bl2 = pk(bl, bl), bh2 = pk(bh, bh);
#pragma unroll
        for (int rp = 0; rp < 8; rp++) { xL[rp] = bl2; xH[rp] = bh2; }
    }
#pragma unroll 4
    for (int j = 0; j < 64; j++) {
        ull wp = we2[j * 32 + lane];
        float wl, wh;
        upk(wp, wl, wh);
        ull wl2 = pk(wl, wl), wh2 = pk(wh, wh);
        const ull* s = S + j * 9;
#pragma unroll
        for (int rp = 0; rp < 8; rp++) {
            ull s2 = s[rp];
            xL[rp] = f2fma(s2, wl2, xL[rp]);
            xH[rp] = f2fma(s2, wh2, xH[rp]);
        }
    }
    __syncwarp();
#pragma unroll
    for (int rp = 0; rp < 8; rp++) {
        S[lane * 9 + rp]        = xL[rp];
        S[(lane + 32) * 9 + rp] = xH[rp];
    }
    __syncwarp();

    ull qL[8], qH[8], kL[8], kH[8], vL[8], vH[8];
#pragma unroll
    for (int rp = 0; rp < 8; rp++) {
        qL[rp] = qH[rp] = kL[rp] = kH[rp] = vL[rp] = vH[rp] = 0ull;
    }
#pragma unroll 2
    for (int j = 0; j < 64; j++) {
        float a, b;
        upk(wq2[j * 32 + lane], a, b);
        ull wql = pk(a, a), wqh = pk(b, b);
        upk(wk2[j * 32 + lane], a, b);
        ull wkl = pk(a, a), wkh = pk(b, b);
        upk(wv2[j * 32 + lane], a, b);
        ull wvl = pk(a, a), wvh = pk(b, b);
        const ull* s = S + j * 9;
#pragma unroll
        for (int rp = 0; rp < 8; rp++) {
            ull s2 = s[rp];
            qL[rp] = f2fma(s2, wql, qL[rp]);
            qH[rp] = f2fma(s2, wqh, qH[rp]);
            kL[rp] = f2fma(s2, wkl, kL[rp]);
            kH[rp] = f2fma(s2, wkh, kH[rp]);
            vL[rp] = f2fma(s2, wvl, vL[rp]);
            vH[rp] = f2fma(s2, wvh, vH[rp]);
        }
    }

#pragma unroll
    for (int rp = 0; rp < 8; rp++) {
        size_t r0 = (size_t)(rows + 2 * rp) * 32 + lane;
        size_t r1 = r0 + 32;
        float a0, a1, b0, b1;
        upk(qL[rp], a0, a1); upk(qH[rp], b0, b1);
        g_q2[r0] = pk(a0, b0); g_q2[r1] = pk(a1, b1);
        upk(kL[rp], a0, a1); upk(kH[rp], b0, b1);
        g_k2[r0] = pk(a0, b0); g_k2[r1] = pk(a1, b1);
        upk(vL[rp], a0, a1); upk(vH[rp], b0, b1);
        g_v2[r0] = pk(a0, b0); g_v2[r1] = pk(a1, b1);
    }
}

// ---------------------------------------------------------------------------
// Kernel 2: KNN — 4 queries per warp share every candidate LDS.128.
// Ballot/flush machinery byte-identical to the validated R3/R5/R7 version;
// all ballots remain in warp-uniform control flow.
// ---------------------------------------------------------------------------
#define KW 8        // warps per block
#define KQ 4        // queries per warp
#define KTS 2048    // candidates per smem tile
#define FSLOTS 80   // 16 top + up to 64 buffered

__device__ __noinline__ void knn_flush(float* wd, int* wi, int& bc,
                                       float& theta, int lane) {
    int n = 16 + bc;
    int i0 = lane, i1 = lane + 32, i2 = lane + 64;
    bool v0 = i0 < n, v1 = i1 < n, v2 = i2 < n;
    float ed0 = v0 ? wd[i0] : 0.f;  int ei0 = v0 ? wi[i0] : 0;
    float ed1 = v1 ? wd[i1] : 0.f;  int ei1 = v1 ? wi[i1] : 0;
    float ed2 = v2 ? wd[i2] : 0.f;  int ei2 = v2 ? wi[i2] : 0;
    int r0 = 0, r1 = 0, r2 = 0;
    for (int j = 0; j < n; j++) {
        float dj = wd[j]; int ij = wi[j];
        r0 += (dj < ed0) || (dj == ed0 && ij < ei0);
        r1 += (dj < ed1) || (dj == ed1 && ij < ei1);
        r2 += (dj < ed2) || (dj == ed2 && ij < ei2);
    }
    __syncwarp();
    if (v0 && r0 < 16) { wd[r0] = ed0; wi[r0] = ei0; }
    if (v1 && r1 < 16) { wd[r1] = ed1; wi[r1] = ei1; }
    if (v2 && r2 < 16) { wd[r2] = ed2; wi[r2] = ei2; }
    __syncwarp();
    theta = wd[15];
    bc = 0;
}

__global__ void __launch_bounds__(256) knn_kernel() {
    extern __shared__ ull ku[];
    float4* tile = (float4*)ku;                          // 32768 B
    float*  fdb  = (float*)(ku + 4096);                  // KW*KQ*80*4
    int*    fib  = (int*)(fdb + KW * KQ * FSLOTS);       // KW*KQ*80*4

    int tid = threadIdx.x, lane = tid & 31, w = tid >> 5;
    int b = blockIdx.y;
    int qbase = (blockIdx.x * KW + w) * KQ;
    const float4* pb4 = g_pos4 + (size_t)b * NN;

    float4 qv[KQ];
    float  th[KQ];
    int    bc[KQ];
    float* wd[KQ];
    int*   wi[KQ];
#pragma unroll
    for (int i = 0; i < KQ; i++) {
        qv[i] = pb4[qbase + i];
        th[i] = FLT_MAX;
        bc[i] = 0;
        wd[i] = fdb + (w * KQ + i) * FSLOTS;
        wi[i] = fib + (w * KQ + i) * FSLOTS;
        if (lane < 16) { wd[i][lane] = FLT_MAX; wi[i][lane] = -1 - lane; }
    }
    __syncwarp();

    for (int t0 = 0; t0 < NN; t0 += KTS) {
        __syncthreads();
        for (int i = tid; i < KTS; i += 256)
            tile[i] = pb4[t0 + i];
        __syncthreads();
#pragma unroll 2
        for (int s = 0; s < KTS / 32; s++) {
            float4 c = tile[s * 32 + lane];
            float d2q[KQ];
            bool  a[KQ];
            bool any = false;
#pragma unroll
            for (int i = 0; i < KQ; i++) {
                float dot = fmaf(qv[i].z, c.z, fmaf(qv[i].y, c.y, qv[i].x * c.x));
                d2q[i] = fmaf(-2.f, dot, qv[i].w + c.w);
                a[i] = d2q[i] < th[i];
                any |= a[i];
            }
            unsigned many = __ballot_sync(0xffffffffu, any);
            if (many) {
                int j = t0 + s * 32 + lane;
#pragma unroll
                for (int i = 0; i < KQ; i++) {
                    if (bc[i] > 32) {
                        knn_flush(wd[i], wi[i], bc[i], th[i], lane);
                        a[i] = d2q[i] < th[i];   // re-test vs tightened theta
                    }
                    unsigned m = __ballot_sync(0xffffffffu, a[i]);
                    if (m) {
                        int off = __popc(m & ((1u << lane) - 1u));
                        if (a[i]) {
                            wd[i][16 + bc[i] + off] = d2q[i];
                            wi[i][16 + bc[i] + off] = j;
                        }
                        bc[i] += __popc(m);
                    }
                }
            }
        }
    }
#pragma unroll
    for (int i = 0; i < KQ; i++) {
        if (bc[i] > 0) knn_flush(wd[i], wi[i], bc[i], th[i], lane);
        if (lane < 16)
            g_idx[((size_t)b * NN + qbase + i) * KK + lane] = wi[i][lane];
    }
}

// ---------------------------------------------------------------------------
// Kernel 3: fused posenc + attn MLPs + softmax + combine + out projection.
// Weights via __ldg from pre-packed globals (frees 48KB smem);
// __launch_bounds__(256,3) lifts occupancy to 3 blocks/SM (regs<=85,
// cold pen values spill to local between Stage B and the combine).
// ---------------------------------------------------------------------------
#define AQ 8
#define SQSTRIDE 640

__device__ __forceinline__ void mv16x64(const ull* __restrict__ Sq,
                                        const ulonglong2* __restrict__ w4, int l,
                                        ull aL[8], ull aH[8]) {
#pragma unroll
    for (int kp = 0; kp < 8; kp++) { aL[kp] = 0ull; aH[kp] = 0ull; }
#pragma unroll 4
    for (int jp = 0; jp < 32; jp++) {
        ulonglong2 wpp = __ldg(&w4[jp * 32 + l]);
        {
            float wl, wh;
            upk(wpp.x, wl, wh);
            ull wl2 = pk(wl, wl), wh2 = pk(wh, wh);
            const ulonglong2* s = (const ulonglong2*)(Sq + (2 * jp) * 10);
#pragma unroll
            for (int kp2 = 0; kp2 < 4; kp2++) {
                ulonglong2 sv = s[kp2];
                aL[2 * kp2]     = f2fma(sv.x, wl2, aL[2 * kp2]);
                aH[2 * kp2]     = f2fma(sv.x, wh2, aH[2 * kp2]);
                aL[2 * kp2 + 1] = f2fma(sv.y, wl2, aL[2 * kp2 + 1]);
                aH[2 * kp2 + 1] = f2fma(sv.y, wh2, aH[2 * kp2 + 1]);
            }
        }
        {
            float wl, wh;
            upk(wpp.y, wl, wh);
            ull wl2 = pk(wl, wl), wh2 = pk(wh, wh);
            const ulonglong2* s = (const ulonglong2*)(Sq + (2 * jp + 1) * 10);
#pragma unroll
            for (int kp2 = 0; kp2 < 4; kp2++) {
                ulonglong2 sv = s[kp2];
                aL[2 * kp2]     = f2fma(sv.x, wl2, aL[2 * kp2]);
                aH[2 * kp2]     = f2fma(sv.x, wh2, aH[2 * kp2]);
                aL[2 * kp2 + 1] = f2fma(sv.y, wl2, aL[2 * kp2 + 1]);
                aH[2 * kp2 + 1] = f2fma(sv.y, wh2, aH[2 * kp2 + 1]);
            }
        }
    }
}

__global__ void __launch_bounds__(256, 3) attn_kernel(
        const float* __restrict__ feat,
        const float* __restrict__ pe_w1, const float* __restrict__ pe_b1,
        const float* __restrict__ pe_b2,
        const float* __restrict__ at_b1, const float* __restrict__ at_b2,
        const float* __restrict__ out_w, const float* __restrict__ out_b,
        float* __restrict__ out) {
    extern __shared__ ull smu[];
    ull* Sp2    = smu;                   // AQ*640
    float* s_pe1 = (float*)(Sp2 + AQ * SQSTRIDE);  // 192
    float* s_b   = s_pe1 + 192;          // 320
    float* relb  = s_b + 320;            // AQ*64
    float* resb  = relb + AQ * 64;       // AQ*64
    int*   idxb  = (int*)(resb + AQ * 64);  // AQ*16

    int tid = threadIdx.x;
    if (tid < 192) s_pe1[tid] = pe_w1[tid];
    if (tid < 64) {
        s_b[tid]       = pe_b1[tid];
        s_b[64 + tid]  = pe_b2[tid];
        s_b[128 + tid] = at_b1[tid];
        s_b[192 + tid] = at_b2[tid];
        s_b[256 + tid] = out_b[tid];
    }

    int wid = tid >> 5;
    int l   = tid & 31;
    int g   = blockIdx.x * AQ + wid;
    int bbase = g & ~(NN - 1);

    float q_lo, q_hi;
    upk(g_q2[(size_t)g * 32 + l], q_lo, q_hi);

    if (l < KK) {
        int ii = g_idx[(size_t)g * KK + l];
        idxb[wid * KK + l] = ii;
        float4 np = g_pos4[bbase + ii];
        float4 qp = g_pos4[g];
        relb[(wid * KK + l) * 4 + 0] = np.x - qp.x;
        relb[(wid * KK + l) * 4 + 1] = np.y - qp.y;
        relb[(wid * KK + l) * 4 + 2] = np.z - qp.z;
    }
    __syncthreads();

    ull* Sq = Sp2 + wid * SQSTRIDE;

    // Stage A: pe1 = relu(rel @ pe_w1 + pe_b1)
    {
        float w0l = s_pe1[l],      w1l = s_pe1[64 + l],  w2l = s_pe1[128 + l];
        float w0h = s_pe1[l + 32], w1h = s_pe1[96 + l],  w2h = s_pe1[160 + l];
        float b1l = s_b[l], b1h = s_b[l + 32];
#pragma unroll
        for (int kp = 0; kp < 8; kp++) {
            const float* ra = relb + (wid * KK + 2 * kp) * 4;
            const float* rb = ra + 4;
            float pa = fmaxf(fmaf(ra[2], w2l, fmaf(ra[1], w1l, fmaf(ra[0], w0l, b1l))), 0.f);
            float pb = fmaxf(fmaf(rb[2], w2l, fmaf(rb[1], w1l, fmaf(rb[0], w0l, b1l))), 0.f);
            Sq[l * 10 + kp] = pk(pa, pb);
            float qa = fmaxf(fmaf(ra[2], w2h, fmaf(ra[1], w1h, fmaf(ra[0], w0h, b1h))), 0.f);
            float qb = fmaxf(fmaf(rb[2], w2h, fmaf(rb[1], w1h, fmaf(rb[0], w0h, b1h))), 0.f);
            Sq[(l + 32) * 10 + kp] = pk(qa, qb);
        }
    }
    __syncwarp();

    // Stage B: posenc = pe1 @ pe_w2 + pe_b2
    ull penL[8], penH[8];
    mv16x64(Sq, g_wpe2, l, penL, penH);
    {
        ull b2l = pk(s_b[64 + l], s_b[64 + l]);
        ull b2h = pk(s_b[64 + l + 32], s_b[64 + l + 32]);
#pragma unroll
        for (int kp = 0; kp < 8; kp++) {
            penL[kp] = f2add(penL[kp], b2l);
            penH[kp] = f2add(penH[kp], b2h);
        }
    }
    __syncwarp();

    // Stage C: h = q - k_feat + posenc
#pragma unroll
    for (int kp = 0; kp < 8; kp++) {
        int i0 = idxb[wid * KK + 2 * kp];
        int i1 = idxb[wid * KK + 2 * kp + 1];
        float k0l, k0h, k1l, k1h;
        upk(g_k2[(size_t)(bbase + i0) * 32 + l], k0l, k0h);
        upk(g_k2[(size_t)(bbase + i1) * 32 + l], k1l, k1h);
        float p0, p1;
        upk(penL[kp], p0, p1);
        Sq[l * 10 + kp] = pk(q_lo - k0l + p0, q_lo - k1l + p1);
        upk(penH[kp], p0, p1);
        Sq[(l + 32) * 10 + kp] = pk(q_hi - k0h + p0, q_hi - k1h + p1);
    }
    __syncwarp();

    // Stage D: a1 = relu(h @ at_w1 + at_b1)
    ull aL[8], aH[8];
    mv16x64(Sq, g_wat1, l, aL, aH);
    __syncwarp();
    {
        float bl = s_b[128 + l], bh = s_b[128 + l + 32];
#pragma unroll
        for (int kp = 0; kp < 8; kp++) {
            float x, y;
            upk(aL[kp], x, y);
            Sq[l * 10 + kp] = pk(fmaxf(x + bl, 0.f), fmaxf(y + bl, 0.f));
            upk(aH[kp], x, y);
            Sq[(l + 32) * 10 + kp] = pk(fmaxf(x + bh, 0.f), fmaxf(y + bh, 0.f));
        }
    }
    __syncwarp();

    // Stage E: logits = (a1 @ at_w2 + at_b2) / 8
    mv16x64(Sq, g_wat2, l, aL, aH);
    float el[KK], eh[KK];
    {
        float bl = s_b[192 + l], bh = s_b[192 + l + 32];
#pragma unroll
        for (int kp = 0; kp < 8; kp++) {
            float x, y;
            upk(aL[kp], x, y);
            el[2 * kp] = (x + bl) * 0.125f; el[2 * kp + 1] = (y + bl) * 0.125f;
            upk(aH[kp], x, y);
            eh[2 * kp] = (x + bh) * 0.125f; eh[2 * kp + 1] = (y + bh) * 0.125f;
        }
    }

    // softmax over K per channel + combine with (v + posenc)
    float ml = el[0], mh = eh[0];
#pragma unroll
    for (int k = 1; k < KK; k++) { ml = fmaxf(ml, el[k]); mh = fmaxf(mh, eh[k]); }
    float sl = 0.f, sh = 0.f;
#pragma unroll
    for (int k = 0; k < KK; k++) {
        el[k] = __expf(el[k] - ml); sl += el[k];
        eh[k] = __expf(eh[k] - mh); sh += eh[k];
    }
    float il = 1.f / sl, ih = 1.f / sh;
    float res_lo = 0.f, res_hi = 0.f;
#pragma unroll
    for (int kp = 0; kp < 8; kp++) {
        int i0 = idxb[wid * KK + 2 * kp];
        int i1 = idxb[wid * KK + 2 * kp + 1];
        float v0l, v0h, v1l, v1h;
        upk(g_v2[(size_t)(bbase + i0) * 32 + l], v0l, v0h);
        upk(g_v2[(size_t)(bbase + i1) * 32 + l], v1l, v1h);
        float p0, p1;
        upk(penL[kp], p0, p1);
        res_lo = fmaf(el[2 * kp] * il,     v0l + p0, res_lo);
        res_lo = fmaf(el[2 * kp + 1] * il, v1l + p1, res_lo);
        upk(penH[kp], p0, p1);
        res_hi = fmaf(eh[2 * kp] * ih,     v0h + p0, res_hi);
        res_hi = fmaf(eh[2 * kp + 1] * ih, v1h + p1, res_hi);
    }
    resb[wid * CC + l] = res_lo;
    resb[wid * CC + l + 32] = res_hi;
    __syncwarp();

    // final: out = res @ out_w + out_b + features (out_w via L1)
    {
        float ol = s_b[256 + l], oh = s_b[256 + l + 32];
#pragma unroll 4
        for (int j = 0; j < 64; j++) {
            float rj = resb[wid * CC + j];
            ol = fmaf(rj, __ldg(&out_w[j * 64 + l]), ol);
            oh = fmaf(rj, __ldg(&out_w[j * 64 + l + 32]), oh);
        }
        out[(size_t)g * CC + l]      = ol + feat[(size_t)g * CC + l];
        out[(size_t)g * CC + l + 32] = oh + feat[(size_t)g * CC + l + 32];
    }
}

// ---------------------------------------------------------------------------
extern "C" void kernel_launch(void* const* d_in, const int* in_sizes, int n_in,
                              void* d_out, int out_size) {
    const float* pos   = (const float*)d_in[0];
    const float* feat  = (const float*)d_in[1];
    const float* emb_w = (const float*)d_in[2];
    const float* emb_b = (const float*)d_in[3];
    const float* wq    = (const float*)d_in[4];
    const float* wk    = (const float*)d_in[5];
    const float* wv    = (const float*)d_in[6];
    const float* pe_w1 = (const float*)d_in[7];
    const float* pe_b1 = (const float*)d_in[8];
    const float* pe_w2 = (const float*)d_in[9];
    const float* pe_b2 = (const float*)d_in[10];
    const float* at_w1 = (const float*)d_in[11];
    const float* at_b1 = (const float*)d_in[12];
    const float* at_w2 = (const float*)d_in[13];
    const float* at_b2 = (const float*)d_in[14];
    const float* out_w = (const float*)d_in[15];
    const float* out_b = (const float*)d_in[16];
    float* out = (float*)d_out;

    int proj_smem = (8192 + PW * 576 + 32) * 8;
    int knn_smem  = 32768 + KW * KQ * FSLOTS * 4 * 2;
    int attn_smem = AQ * SQSTRIDE * 8
                  + (192 + 320 + AQ * 64 * 2) * 4 + AQ * KK * 4;
    cudaFuncSetAttribute(proj_kernel, cudaFuncAttributeMaxDynamicSharedMemorySize, proj_smem);
    cudaFuncSetAttribute(knn_kernel, cudaFuncAttributeMaxDynamicSharedMemorySize, knn_smem);
    cudaFuncSetAttribute(attn_kernel, cudaFuncAttributeMaxDynamicSharedMemorySize, attn_smem);

    prep_kernel<<<BN / 256, 256>>>(pos);
    pack_kernel<<<4, 256>>>(pe_w2, at_w1, at_w2);
    proj_kernel<<<BN / (PW * 16), 128, proj_smem>>>(feat, emb_w, emb_b, wq, wk, wv);
    knn_kernel<<<dim3(NN / (KW * KQ), BB), 256, knn_smem>>>();
    attn_kernel<<<BN / AQ, 256, attn_smem>>>(feat, pe_w1, pe_b1, pe_b2,
                                             at_b1, at_b2, out_w, out_b, out);
}

// round 9
// speedup vs baseline: 1.7359x; 1.7359x over previous
#include <cuda_runtime.h>
#include <math.h>
#include <float.h>

#define BB 2
#define NN 8192
#define KK 16
#define CC 64
#define BN (BB*NN)

typedef unsigned long long ull;

__device__ __forceinline__ ull pk(float a, float b) {
    ull d; asm("mov.b64 %0,{%1,%2};" : "=l"(d) : "f"(a), "f"(b)); return d;
}
__device__ __forceinline__ void upk(ull s, float& a, float& b) {
    asm("mov.b64 {%0,%1},%2;" : "=f"(a), "=f"(b) : "l"(s));
}
__device__ __forceinline__ ull f2fma(ull a, ull b, ull c) {
    ull d; asm("fma.rn.f32x2 %0,%1,%2,%3;" : "=l"(d) : "l"(a), "l"(b), "l"(c)); return d;
}
__device__ __forceinline__ ull f2add(ull a, ull b) {
    ull d; asm("add.rn.f32x2 %0,%1,%2;" : "=l"(d) : "l"(a), "l"(b)); return d;
}

// sortable-float mapping: exact total order on f32 as u32
__device__ __forceinline__ unsigned senc(float d) {
    unsigned u = __float_as_uint(d);
    unsigned mask = ((unsigned)(((int)u) >> 31)) | 0x80000000u;
    return u ^ mask;
}
__device__ __forceinline__ float sdec(unsigned hi) {
    unsigned u = (hi & 0x80000000u) ? (hi ^ 0x80000000u) : ~hi;
    return __uint_as_float(u);
}

// scratch (device globals — no runtime allocation)
__device__ ull    g_q2[BN*32];     // (q[row][l], q[row][l+32])
__device__ ull    g_k2[BN*32];
__device__ ull    g_v2[BN*32];
__device__ int    g_idx[BN*KK];
__device__ float4 g_pos4[BN];      // (x, y, z, ||p||^2)

// ---------------------------------------------------------------------------
// Kernel 0: precompute pos4 with the exact fmaf chain used everywhere.
// ---------------------------------------------------------------------------
__global__ void prep_kernel(const float* __restrict__ pos) {
    int i = blockIdx.x * 256 + threadIdx.x;
    float x = pos[3 * i], y = pos[3 * i + 1], z = pos[3 * i + 2];
    g_pos4[i] = make_float4(x, y, z, fmaf(z, z, fmaf(y, y, x * x)));
}

// ---------------------------------------------------------------------------
// Kernel 1: x = feat@emb_w + emb_b ; q/k/v = x@wq/wk/wv.  (unchanged)
// ---------------------------------------------------------------------------
#define PW 4
__global__ void __launch_bounds__(128) proj_kernel(
        const float* __restrict__ feat,
        const float* __restrict__ emb_w, const float* __restrict__ emb_b,
        const float* __restrict__ wq, const float* __restrict__ wk,
        const float* __restrict__ wv) {
    extern __shared__ ull pu[];
    ull* we2 = pu;              // 2048
    ull* wq2 = pu + 2048;
    ull* wk2 = pu + 4096;
    ull* wv2 = pu + 6144;
    ull* Sbase = pu + 8192;     // PW * 576
    ull* ebp = Sbase + PW * 576; // 32

    int tid = threadIdx.x, lane = tid & 31, w = tid >> 5;
    for (int e = tid; e < 2048; e += 128) {
        int j = e >> 5, l2 = e & 31;
        we2[e] = pk(emb_w[j * 64 + l2], emb_w[j * 64 + l2 + 32]);
        wq2[e] = pk(wq[j * 64 + l2],   wq[j * 64 + l2 + 32]);
        wk2[e] = pk(wk[j * 64 + l2],   wk[j * 64 + l2 + 32]);
        wv2[e] = pk(wv[j * 64 + l2],   wv[j * 64 + l2 + 32]);
    }
    if (tid < 32) ebp[tid] = pk(emb_b[tid], emb_b[tid + 32]);

    int rows = (blockIdx.x * PW + w) * 16;
    ull* S = Sbase + w * 576;

#pragma unroll
    for (int rp = 0; rp < 8; rp++) {
        const float* f0 = feat + (size_t)(rows + 2 * rp) * 64;
        const float* f1 = f0 + 64;
        S[lane * 9 + rp]        = pk(f0[lane],      f1[lane]);
        S[(lane + 32) * 9 + rp] = pk(f0[lane + 32], f1[lane + 32]);
    }
    __syncthreads();

    ull xL[8], xH[8];
    {
        float bl, bh;
        upk(ebp[lane], bl, bh);
        ull bl2 = pk(bl, bl), bh2 = pk(bh, bh);
#pragma unroll
        for (int rp = 0; rp < 8; rp++) { xL[rp] = bl2; xH[rp] = bh2; }
    }
#pragma unroll 4
    for (int j = 0; j < 64; j++) {
        ull wp = we2[j * 32 + lane];
        float wl, wh;
        upk(wp, wl, wh);
        ull wl2 = pk(wl, wl), wh2 = pk(wh, wh);
        const ull* s = S + j * 9;
#pragma unroll
        for (int rp = 0; rp < 8; rp++) {
            ull s2 = s[rp];
            xL[rp] = f2fma(s2, wl2, xL[rp]);
            xH[rp] = f2fma(s2, wh2, xH[rp]);
        }
    }
    __syncwarp();
#pragma unroll
    for (int rp = 0; rp < 8; rp++) {
        S[lane * 9 + rp]        = xL[rp];
        S[(lane + 32) * 9 + rp] = xH[rp];
    }
    __syncwarp();

    ull qL[8], qH[8], kL[8], kH[8], vL[8], vH[8];
#pragma unroll
    for (int rp = 0; rp < 8; rp++) {
        qL[rp] = qH[rp] = kL[rp] = kH[rp] = vL[rp] = vH[rp] = 0ull;
    }
#pragma unroll 2
    for (int j = 0; j < 64; j++) {
        float a, b;
        upk(wq2[j * 32 + lane], a, b);
        ull wql = pk(a, a), wqh = pk(b, b);
        upk(wk2[j * 32 + lane], a, b);
        ull wkl = pk(a, a), wkh = pk(b, b);
        upk(wv2[j * 32 + lane], a, b);
        ull wvl = pk(a, a), wvh = pk(b, b);
        const ull* s = S + j * 9;
#pragma unroll
        for (int rp = 0; rp < 8; rp++) {
            ull s2 = s[rp];
            qL[rp] = f2fma(s2, wql, qL[rp]);
            qH[rp] = f2fma(s2, wqh, qH[rp]);
            kL[rp] = f2fma(s2, wkl, kL[rp]);
            kH[rp] = f2fma(s2, wkh, kH[rp]);
            vL[rp] = f2fma(s2, wvl, vL[rp]);
            vH[rp] = f2fma(s2, wvh, vH[rp]);
        }
    }

#pragma unroll
    for (int rp = 0; rp < 8; rp++) {
        size_t r0 = (size_t)(rows + 2 * rp) * 32 + lane;
        size_t r1 = r0 + 32;
        float a0, a1, b0, b1;
        upk(qL[rp], a0, a1); upk(qH[rp], b0, b1);
        g_q2[r0] = pk(a0, b0); g_q2[r1] = pk(a1, b1);
        upk(kL[rp], a0, a1); upk(kH[rp], b0, b1);
        g_k2[r0] = pk(a0, b0); g_k2[r1] = pk(a1, b1);
        upk(vL[rp], a0, a1); upk(vH[rp], b0, b1);
        g_v2[r0] = pk(a0, b0); g_v2[r1] = pk(a1, b1);
    }
}

// ---------------------------------------------------------------------------
// Kernel 2: KNN — R7 2q/warp scan + u64-key flush (single lexicographic key
// (sortable(d2), idx): exact order, unique keys -> rank is a permutation).
// Theta primed exactly from candidates 0..31. Trigger bc>16, capacity 48.
// ---------------------------------------------------------------------------
#define KW 8        // warps per block
#define KTS 2048    // candidates per smem tile
#define FSLOTS 64   // 16 top + up to 48 buffered

__device__ __noinline__ void knn_flush(ull* kd, int& bc, float& theta, int lane) {
    int n = 16 + bc;
    ull k0 = (lane < n) ? kd[lane] : ~0ull;
    ull k1 = (lane + 32 < n) ? kd[lane + 32] : ~0ull;
    int r0 = 0, r1 = 0;
    for (int j = 0; j < n; j++) {
        ull kj = kd[j];
        r0 += (kj < k0);
        r1 += (kj < k1);
    }
    __syncwarp();
    if (r0 < 16) kd[r0] = k0;   // invalid/out-of-top keys rank >= 16
    if (r1 < 16) kd[r1] = k1;
    __syncwarp();
    theta = sdec((unsigned)(kd[15] >> 32));
    bc = 0;
}

__global__ void __launch_bounds__(256) knn_kernel() {
    extern __shared__ ull ku[];
    float4* tile = (float4*)ku;              // 4096 ull = 32768 B
    ull* kbuf = ku + 4096;                   // KW*2*64 ull = 8192 B

    int tid = threadIdx.x, lane = tid & 31, w = tid >> 5;
    int b = blockIdx.y;
    int q0 = (blockIdx.x * KW + w) * 2;
    int q1 = q0 + 1;
    const float4* pb4 = g_pos4 + (size_t)b * NN;
    float4 qv0 = pb4[q0];
    float4 qv1 = pb4[q1];

    ull* kd0 = kbuf + (w * 2 + 0) * FSLOTS;
    ull* kd1 = kbuf + (w * 2 + 1) * FSLOTS;
    if (lane < 16) {
        // init keys: larger than any real finite-d2 key, mutually distinct
        kd0[lane] = (((ull)0xFF7FFFFFu) << 32) | (unsigned)lane;
        kd1[lane] = (((ull)0xFF7FFFFFu) << 32) | (unsigned)lane;
    }
    __syncwarp();

    float th0 = FLT_MAX, th1 = FLT_MAX;
    int bc0 = 0, bc1 = 0;

    for (int t0 = 0; t0 < NN; t0 += KTS) {
        __syncthreads();
        for (int i = tid; i < KTS; i += 256)
            tile[i] = pb4[t0 + i];
        __syncthreads();

        int s = 0;
        if (t0 == 0) {
            // prime theta exactly from candidates 0..31
            float4 c = tile[lane];
            float dot0 = fmaf(qv0.z, c.z, fmaf(qv0.y, c.y, qv0.x * c.x));
            float dot1 = fmaf(qv1.z, c.z, fmaf(qv1.y, c.y, qv1.x * c.x));
            float d20 = fmaf(-2.f, dot0, qv0.w + c.w);
            float d21 = fmaf(-2.f, dot1, qv1.w + c.w);
            kd0[16 + lane] = (((ull)senc(d20)) << 32) | (unsigned)lane;
            kd1[16 + lane] = (((ull)senc(d21)) << 32) | (unsigned)lane;
            __syncwarp();
            bc0 = 32; knn_flush(kd0, bc0, th0, lane);
            bc1 = 32; knn_flush(kd1, bc1, th1, lane);
            s = 1;
        }

        for (; s < KTS / 32; s++) {
            float4 c = tile[s * 32 + lane];
            float dot0 = fmaf(qv0.z, c.z, fmaf(qv0.y, c.y, qv0.x * c.x));
            float dot1 = fmaf(qv1.z, c.z, fmaf(qv1.y, c.y, qv1.x * c.x));
            float d20 = fmaf(-2.f, dot0, qv0.w + c.w);
            float d21 = fmaf(-2.f, dot1, qv1.w + c.w);
            bool a0 = d20 < th0;
            bool a1 = d21 < th1;
            if (__ballot_sync(0xffffffffu, a0 | a1)) {
                if (bc0 > 16) {
                    knn_flush(kd0, bc0, th0, lane);
                    a0 = d20 < th0;   // re-test vs tightened theta (exact)
                }
                if (bc1 > 16) {
                    knn_flush(kd1, bc1, th1, lane);
                    a1 = d21 < th1;
                }
                unsigned m0 = __ballot_sync(0xffffffffu, a0);
                unsigned m1 = __ballot_sync(0xffffffffu, a1);
                int j = t0 + s * 32 + lane;
                if (m0) {
                    int off = __popc(m0 & ((1u << lane) - 1u));
                    if (a0) kd0[16 + bc0 + off] = (((ull)senc(d20)) << 32) | (unsigned)j;
                    bc0 += __popc(m0);
                }
                if (m1) {
                    int off = __popc(m1 & ((1u << lane) - 1u));
                    if (a1) kd1[16 + bc1 + off] = (((ull)senc(d21)) << 32) | (unsigned)j;
                    bc1 += __popc(m1);
                }
            }
        }
    }
    if (bc0 > 0) knn_flush(kd0, bc0, th0, lane);
    if (bc1 > 0) knn_flush(kd1, bc1, th1, lane);
    if (lane < 16) {
        g_idx[((size_t)b * NN + q0) * KK + lane] = (int)(unsigned)(kd0[lane] & 0xFFFFFFFFu);
        g_idx[((size_t)b * NN + q1) * KK + lane] = (int)(unsigned)(kd1[lane] & 0xFFFFFFFFu);
    }
}

// ---------------------------------------------------------------------------
// Kernel 3: fused posenc + attn MLPs + softmax + combine + out projection.
// (exact R7 version: weights in smem as ulonglong2 pairs; measured 166 us)
// ---------------------------------------------------------------------------
#define AQ 8
#define SQSTRIDE 640

__device__ __forceinline__ void mv16x64(const ull* __restrict__ Sq,
                                        const ulonglong2* __restrict__ w4, int l,
                                        ull aL[8], ull aH[8]) {
#pragma unroll
    for (int kp = 0; kp < 8; kp++) { aL[kp] = 0ull; aH[kp] = 0ull; }
#pragma unroll 4
    for (int jp = 0; jp < 32; jp++) {
        ulonglong2 wpp = w4[jp * 32 + l];
        {
            float wl, wh;
            upk(wpp.x, wl, wh);
            ull wl2 = pk(wl, wl), wh2 = pk(wh, wh);
            const ulonglong2* s = (const ulonglong2*)(Sq + (2 * jp) * 10);
#pragma unroll
            for (int kp2 = 0; kp2 < 4; kp2++) {
                ulonglong2 sv = s[kp2];
                aL[2 * kp2]     = f2fma(sv.x, wl2, aL[2 * kp2]);
                aH[2 * kp2]     = f2fma(sv.x, wh2, aH[2 * kp2]);
                aL[2 * kp2 + 1] = f2fma(sv.y, wl2, aL[2 * kp2 + 1]);
                aH[2 * kp2 + 1] = f2fma(sv.y, wh2, aH[2 * kp2 + 1]);
            }
        }
        {
            float wl, wh;
            upk(wpp.y, wl, wh);
            ull wl2 = pk(wl, wl), wh2 = pk(wh, wh);
            const ulonglong2* s = (const ulonglong2*)(Sq + (2 * jp + 1) * 10);
#pragma unroll
            for (int kp2 = 0; kp2 < 4; kp2++) {
                ulonglong2 sv = s[kp2];
                aL[2 * kp2]     = f2fma(sv.x, wl2, aL[2 * kp2]);
                aH[2 * kp2]     = f2fma(sv.x, wh2, aH[2 * kp2]);
                aL[2 * kp2 + 1] = f2fma(sv.y, wl2, aL[2 * kp2 + 1]);
                aH[2 * kp2 + 1] = f2fma(sv.y, wh2, aH[2 * kp2 + 1]);
            }
        }
    }
}

__global__ void __launch_bounds__(256) attn_kernel(
        const float* __restrict__ feat,
        const float* __restrict__ pe_w1, const float* __restrict__ pe_b1,
        const float* __restrict__ pe_w2, const float* __restrict__ pe_b2,
        const float* __restrict__ at_w1, const float* __restrict__ at_b1,
        const float* __restrict__ at_w2, const float* __restrict__ at_b2,
        const float* __restrict__ out_w, const float* __restrict__ out_b,
        float* __restrict__ out) {
    extern __shared__ ull smu[];
    ulonglong2* w4_pe2 = (ulonglong2*)smu;           // 1024 u2 (2048 ull)
    ulonglong2* w4_at1 = (ulonglong2*)(smu + 2048);
    ulonglong2* w4_at2 = (ulonglong2*)(smu + 4096);
    ull* Sp2    = smu + 6144;            // AQ*640
    float* s_pe1 = (float*)(Sp2 + AQ * SQSTRIDE);  // 192
    float* s_b   = s_pe1 + 192;          // 320
    float* relb  = s_b + 320;            // AQ*64
    float* resb  = relb + AQ * 64;       // AQ*64
    int*   idxb  = (int*)(resb + AQ * 64);  // AQ*16

    int tid = threadIdx.x;
    for (int e = tid; e < 1024; e += 256) {
        int jp = e >> 5, l2 = e & 31;
        int j0 = 2 * jp, j1 = 2 * jp + 1;
        w4_pe2[e] = make_ulonglong2(pk(pe_w2[j0 * 64 + l2], pe_w2[j0 * 64 + l2 + 32]),
                                    pk(pe_w2[j1 * 64 + l2], pe_w2[j1 * 64 + l2 + 32]));
        w4_at1[e] = make_ulonglong2(pk(at_w1[j0 * 64 + l2], at_w1[j0 * 64 + l2 + 32]),
                                    pk(at_w1[j1 * 64 + l2], at_w1[j1 * 64 + l2 + 32]));
        w4_at2[e] = make_ulonglong2(pk(at_w2[j0 * 64 + l2], at_w2[j0 * 64 + l2 + 32]),
                                    pk(at_w2[j1 * 64 + l2], at_w2[j1 * 64 + l2 + 32]));
    }
    if (tid < 192) s_pe1[tid] = pe_w1[tid];
    if (tid < 64) {
        s_b[tid]       = pe_b1[tid];
        s_b[64 + tid]  = pe_b2[tid];
        s_b[128 + tid] = at_b1[tid];
        s_b[192 + tid] = at_b2[tid];
        s_b[256 + tid] = out_b[tid];
    }

    int wid = tid >> 5;
    int l   = tid & 31;
    int g   = blockIdx.x * AQ + wid;
    int bbase = g & ~(NN - 1);

    float q_lo, q_hi;
    upk(g_q2[(size_t)g * 32 + l], q_lo, q_hi);

    if (l < KK) {
        int ii = g_idx[(size_t)g * KK + l];
        idxb[wid * KK + l] = ii;
        float4 np = g_pos4[bbase + ii];
        float4 qp = g_pos4[g];
        relb[(wid * KK + l) * 4 + 0] = np.x - qp.x;
        relb[(wid * KK + l) * 4 + 1] = np.y - qp.y;
        relb[(wid * KK + l) * 4 + 2] = np.z - qp.z;
    }
    __syncthreads();

    ull* Sq = Sp2 + wid * SQSTRIDE;

    // Stage A: pe1 = relu(rel @ pe_w1 + pe_b1)
    {
        float w0l = s_pe1[l],      w1l = s_pe1[64 + l],  w2l = s_pe1[128 + l];
        float w0h = s_pe1[l + 32], w1h = s_pe1[96 + l],  w2h = s_pe1[160 + l];
        float b1l = s_b[l], b1h = s_b[l + 32];
#pragma unroll
        for (int kp = 0; kp < 8; kp++) {
            const float* ra = relb + (wid * KK + 2 * kp) * 4;
            const float* rb = ra + 4;
            float pa = fmaxf(fmaf(ra[2], w2l, fmaf(ra[1], w1l, fmaf(ra[0], w0l, b1l))), 0.f);
            float pb = fmaxf(fmaf(rb[2], w2l, fmaf(rb[1], w1l, fmaf(rb[0], w0l, b1l))), 0.f);
            Sq[l * 10 + kp] = pk(pa, pb);
            float qa = fmaxf(fmaf(ra[2], w2h, fmaf(ra[1], w1h, fmaf(ra[0], w0h, b1h))), 0.f);
            float qb = fmaxf(fmaf(rb[2], w2h, fmaf(rb[1], w1h, fmaf(rb[0], w0h, b1h))), 0.f);
            Sq[(l + 32) * 10 + kp] = pk(qa, qb);
        }
    }
    __syncwarp();

    // Stage B: posenc = pe1 @ pe_w2 + pe_b2
    ull penL[8], penH[8];
    mv16x64(Sq, w4_pe2, l, penL, penH);
    {
        ull b2l = pk(s_b[64 + l], s_b[64 + l]);
        ull b2h = pk(s_b[64 + l + 32], s_b[64 + l + 32]);
#pragma unroll
        for (int kp = 0; kp < 8; kp++) {
            penL[kp] = f2add(penL[kp], b2l);
            penH[kp] = f2add(penH[kp], b2h);
        }
    }
    __syncwarp();

    // Stage C: h = q - k_feat + posenc
#pragma unroll
    for (int kp = 0; kp < 8; kp++) {
        int i0 = idxb[wid * KK + 2 * kp];
        int i1 = idxb[wid * KK + 2 * kp + 1];
        float k0l, k0h, k1l, k1h;
        upk(g_k2[(size_t)(bbase + i0) * 32 + l], k0l, k0h);
        upk(g_k2[(size_t)(bbase + i1) * 32 + l], k1l, k1h);
        float p0, p1;
        upk(penL[kp], p0, p1);
        Sq[l * 10 + kp] = pk(q_lo - k0l + p0, q_lo - k1l + p1);
        upk(penH[kp], p0, p1);
        Sq[(l + 32) * 10 + kp] = pk(q_hi - k0h + p0, q_hi - k1h + p1);
    }
    __syncwarp();

    // Stage D: a1 = relu(h @ at_w1 + at_b1)
    ull aL[8], aH[8];
    mv16x64(Sq, w4_at1, l, aL, aH);
    __syncwarp();
    {
        float bl = s_b[128 + l], bh = s_b[128 + l + 32];
#pragma unroll
        for (int kp = 0; kp < 8; kp++) {
            float x, y;
            upk(aL[kp], x, y);
            Sq[l * 10 + kp] = pk(fmaxf(x + bl, 0.f), fmaxf(y + bl, 0.f));
            upk(aH[kp], x, y);
            Sq[(l + 32) * 10 + kp] = pk(fmaxf(x + bh, 0.f), fmaxf(y + bh, 0.f));
        }
    }
    __syncwarp();

    // Stage E: logits = (a1 @ at_w2 + at_b2) / 8
    mv16x64(Sq, w4_at2, l, aL, aH);
    float el[KK], eh[KK];
    {
        float bl = s_b[192 + l], bh = s_b[192 + l + 32];
#pragma unroll
        for (int kp = 0; kp < 8; kp++) {
            float x, y;
            upk(aL[kp], x, y);
            el[2 * kp] = (x + bl) * 0.125f; el[2 * kp + 1] = (y + bl) * 0.125f;
            upk(aH[kp], x, y);
            eh[2 * kp] = (x + bh) * 0.125f; eh[2 * kp + 1] = (y + bh) * 0.125f;
        }
    }

    // softmax over K per channel + combine with (v + posenc)
    float ml = el[0], mh = eh[0];
#pragma unroll
    for (int k = 1; k < KK; k++) { ml = fmaxf(ml, el[k]); mh = fmaxf(mh, eh[k]); }
    float sl = 0.f, sh = 0.f;
#pragma unroll
    for (int k = 0; k < KK; k++) {
        el[k] = __expf(el[k] - ml); sl += el[k];
        eh[k] = __expf(eh[k] - mh); sh += eh[k];
    }
    float il = 1.f / sl, ih = 1.f / sh;
    float res_lo = 0.f, res_hi = 0.f;
#pragma unroll
    for (int kp = 0; kp < 8; kp++) {
        int i0 = idxb[wid * KK + 2 * kp];
        int i1 = idxb[wid * KK + 2 * kp + 1];
        float v0l, v0h, v1l, v1h;
        upk(g_v2[(size_t)(bbase + i0) * 32 + l], v0l, v0h);
        upk(g_v2[(size_t)(bbase + i1) * 32 + l], v1l, v1h);
        float p0, p1;
        upk(penL[kp], p0, p1);
        res_lo = fmaf(el[2 * kp] * il,     v0l + p0, res_lo);
        res_lo = fmaf(el[2 * kp + 1] * il, v1l + p1, res_lo);
        upk(penH[kp], p0, p1);
        res_hi = fmaf(eh[2 * kp] * ih,     v0h + p0, res_hi);
        res_hi = fmaf(eh[2 * kp + 1] * ih, v1h + p1, res_hi);
    }
    resb[wid * CC + l] = res_lo;
    resb[wid * CC + l + 32] = res_hi;
    __syncwarp();

    // final: out = res @ out_w + out_b + features (out_w via L1)
    {
        float ol = s_b[256 + l], oh = s_b[256 + l + 32];
#pragma unroll 4
        for (int j = 0; j < 64; j++) {
            float rj = resb[wid * CC + j];
            ol = fmaf(rj, __ldg(&out_w[j * 64 + l]), ol);
            oh = fmaf(rj, __ldg(&out_w[j * 64 + l + 32]), oh);
        }
        out[(size_t)g * CC + l]      = ol + feat[(size_t)g * CC + l];
        out[(size_t)g * CC + l + 32] = oh + feat[(size_t)g * CC + l + 32];
    }
}

// ---------------------------------------------------------------------------
extern "C" void kernel_launch(void* const* d_in, const int* in_sizes, int n_in,
                              void* d_out, int out_size) {
    const float* pos   = (const float*)d_in[0];
    const float* feat  = (const float*)d_in[1];
    const float* emb_w = (const float*)d_in[2];
    const float* emb_b = (const float*)d_in[3];
    const float* wq    = (const float*)d_in[4];
    const float* wk    = (const float*)d_in[5];
    const float* wv    = (const float*)d_in[6];
    const float* pe_w1 = (const float*)d_in[7];
    const float* pe_b1 = (const float*)d_in[8];
    const float* pe_w2 = (const float*)d_in[9];
    const float* pe_b2 = (const float*)d_in[10];
    const float* at_w1 = (const float*)d_in[11];
    const float* at_b1 = (const float*)d_in[12];
    const float* at_w2 = (const float*)d_in[13];
    const float* at_b2 = (const float*)d_in[14];
    const float* out_w = (const float*)d_in[15];
    const float* out_b = (const float*)d_in[16];
    float* out = (float*)d_out;

    int proj_smem = (8192 + PW * 576 + 32) * 8;
    int knn_smem  = 32768 + KW * 2 * FSLOTS * 8;
    int attn_smem = (6144 + AQ * SQSTRIDE) * 8
                  + (192 + 320 + AQ * 64 * 2) * 4 + AQ * KK * 4;
    cudaFuncSetAttribute(proj_kernel, cudaFuncAttributeMaxDynamicSharedMemorySize, proj_smem);
    cudaFuncSetAttribute(knn_kernel, cudaFuncAttributeMaxDynamicSharedMemorySize, knn_smem);
    cudaFuncSetAttribute(attn_kernel, cudaFuncAttributeMaxDynamicSharedMemorySize, attn_smem);

    prep_kernel<<<BN / 256, 256>>>(pos);
    proj_kernel<<<BN / (PW * 16), 128, proj_smem>>>(feat, emb_w, emb_b, wq, wk, wv);
    knn_kernel<<<dim3(NN / (KW * 2), BB), 256, knn_smem>>>();
    attn_kernel<<<BN / AQ, 256, attn_smem>>>(feat, pe_w1, pe_b1, pe_w2, pe_b2,
                                             at_w1, at_b1, at_w2, at_b2, out_w, out_b, out);
}